// round 11
// baseline (speedup 1.0000x reference)
#include <cuda_runtime.h>
#include <math.h>

#define BB 512
#define TT 2048
#define CC 64

#define GRID_PERSIST 1184          // 148 SMs * 8 CTAs/SM (256 thr, 32 regs)
#define NPAIRS (BB * TT / 2)       // 524288 row-pairs
#define CHUNKS (NPAIRS / 16)       // 32768 chunks of 16 row-pairs (256 thr each)

__device__ int   g_i0[TT];
__device__ float g_w0[TT];
__device__ float g_w1[TT];
__device__ float g_ca[BB];
__device__ float g_sa[BB];
__device__ float g_mask[CC];

// One-block prep with parallel scan.
__global__ void __launch_bounds__(512) prep_kernel(
    const float* __restrict__ scale_u,
    const float* __restrict__ warp_noise,
    const float* __restrict__ angle_u,
    const float* __restrict__ chmask_u)
{
    __shared__ float cum[TT];
    __shared__ float wsum[8];
    const int tid  = threadIdx.x;         // 512 threads
    const int lane = tid & 31;
    const int wid  = tid >> 5;
    const float k = 0.2f / (float)TT;     // TW_SIGMA / T

    float loc[8];
    float myTotal = 0.f, inc = 0.f;
    if (tid < 256) {
        float run = 0.f;
        #pragma unroll
        for (int i = 0; i < 8; i++) {
            run += warp_noise[tid * 8 + i] * k;
            loc[i] = run;
        }
        myTotal = run;
        inc = myTotal;
        #pragma unroll
        for (int d = 1; d < 32; d <<= 1) {
            float o = __shfl_up_sync(0xffffffffu, inc, d);
            if (lane >= d) inc += o;
        }
        if (lane == 31) wsum[wid] = inc;
    }
    __syncthreads();
    if (tid == 0) {
        float a = 0.f;
        #pragma unroll
        for (int j = 0; j < 8; j++) { float v = wsum[j]; wsum[j] = a; a += v; }
    }
    __syncthreads();
    if (tid < 256) {
        float excl = (inc - myTotal) + wsum[wid];
        #pragma unroll
        for (int i = 0; i < 8; i++) cum[tid * 8 + i] = excl + loc[i];
    }
    __syncthreads();

    const float c0    = cum[0];
    const float denom = (cum[TT - 1] - c0) + 1e-8f;
    const float scale = 0.9f + scale_u[0] * 0.2f;

    if (tid < 256) {
        #pragma unroll
        for (int i = 0; i < 8; i++) {
            int t = tid * 8 + i;
            float w  = (cum[t] - c0) / denom;
            float tw = (float)t / (float)(TT - 1) + 0.2f * w;
            tw = fminf(fmaxf(tw, 0.f), 1.f);
            float pos = tw * (float)(TT - 1);
            int i0 = (int)floorf(pos);
            i0 = min(max(i0, 0), TT - 2);
            float frac = pos - (float)i0;
            g_i0[t] = i0;
            g_w0[t] = scale * (1.f - frac);
            g_w1[t] = scale * frac;
        }
    }

    {   // per-batch rotation (512 threads == B)
        float ang = angle_u[tid] * 6.283185307179586f - 3.141592653589793f;
        g_ca[tid] = cosf(ang);
        g_sa[tid] = sinf(ang);
    }
    if (tid < CC) g_mask[tid] = (chmask_u[tid] > 0.1f) ? 1.f : 0.f;
}

// Persistent fused main pass: one full wave of CTAs (148*8), grid-stride over
// chunks. Per-iteration body identical to the converged R5 pattern:
// 16 contiguous threads per 64-channel row, 2 adjacent t-rows per thread,
// 8 front-batched coalesced LDG.128, streaming stores.
__global__ void __launch_bounds__(256) aug_kernel(
    const float4* __restrict__ x,
    const float4* __restrict__ nz,
    float4* __restrict__ out)
{
    const int tid   = threadIdx.x;
    const int lane  = tid & 15;            // float4 index within row
    const int sub   = tid >> 4;            // 0..15: row-pair within chunk

    for (int chunk = blockIdx.x; chunk < CHUNKS; chunk += GRID_PERSIST) {
        const int p    = chunk * 16 + sub; // row-pair index
        const int row0 = p * 2;            // b*T + t0 (t0 even)
        const int t0   = row0 & (TT - 1);
        const int t1   = t0 + 1;
        const int b    = row0 >> 11;       // T = 2048 = 2^11

        const int   i0a = g_i0[t0];
        const int   i0b = g_i0[t1];
        const float w0a = g_w0[t0], w1a = g_w1[t0];
        const float w0b = g_w0[t1], w1b = g_w1[t1];

        const size_t bb    = (size_t)b * TT;
        const size_t baseA = (bb + (size_t)i0a) * 16 + (size_t)lane;
        const size_t baseB = (bb + (size_t)i0b) * 16 + (size_t)lane;

        // 8 independent coalesced 128-bit loads, front-batched for MLP
        const float4 xa0 = __ldg(x  + baseA);
        const float4 xa1 = __ldg(x  + baseA + 16);
        const float4 xb0 = __ldg(x  + baseB);
        const float4 xb1 = __ldg(x  + baseB + 16);
        const float4 na0 = __ldg(nz + baseA);
        const float4 na1 = __ldg(nz + baseA + 16);
        const float4 nb0 = __ldg(nz + baseB);
        const float4 nb1 = __ldg(nz + baseB + 16);

        const float J = 0.01f;
        float4 va, vb;
        va.x = w0a * fmaf(J, na0.x, xa0.x) + w1a * fmaf(J, na1.x, xa1.x);
        va.y = w0a * fmaf(J, na0.y, xa0.y) + w1a * fmaf(J, na1.y, xa1.y);
        va.z = w0a * fmaf(J, na0.z, xa0.z) + w1a * fmaf(J, na1.z, xa1.z);
        va.w = w0a * fmaf(J, na0.w, xa0.w) + w1a * fmaf(J, na1.w, xa1.w);
        vb.x = w0b * fmaf(J, nb0.x, xb0.x) + w1b * fmaf(J, nb1.x, xb1.x);
        vb.y = w0b * fmaf(J, nb0.y, xb0.y) + w1b * fmaf(J, nb1.y, xb1.y);
        vb.z = w0b * fmaf(J, nb0.z, xb0.z) + w1b * fmaf(J, nb1.z, xb1.z);
        vb.w = w0b * fmaf(J, nb0.w, xb0.w) + w1b * fmaf(J, nb1.w, xb1.w);

        if (lane == 0) {  // channels 0,1 rotation (both rows, same batch)
            const float ca = g_ca[b], sa = g_sa[b];
            float r0 = ca * va.x - sa * va.y;
            float r1 = sa * va.x + ca * va.y;
            va.x = r0; va.y = r1;
            r0 = ca * vb.x - sa * vb.y;
            r1 = sa * vb.x + ca * vb.y;
            vb.x = r0; vb.y = r1;
        }

        const float4 m = reinterpret_cast<const float4*>(g_mask)[lane];
        va.x *= m.x; va.y *= m.y; va.z *= m.z; va.w *= m.w;
        vb.x *= m.x; vb.y *= m.y; vb.z *= m.z; vb.w *= m.w;

        const size_t ob = (size_t)row0 * 16 + (size_t)lane;
        __stcs(out + ob,      va);
        __stcs(out + ob + 16, vb);
    }
}

extern "C" void kernel_launch(void* const* d_in, const int* in_sizes, int n_in,
                              void* d_out, int out_size)
{
    const float* x        = (const float*)d_in[0];
    const float* noise    = (const float*)d_in[1];
    const float* scale_u  = (const float*)d_in[2];
    const float* warp_n   = (const float*)d_in[3];
    const float* angle_u  = (const float*)d_in[4];
    const float* chmask_u = (const float*)d_in[5];
    float* out = (float*)d_out;

    prep_kernel<<<1, 512>>>(scale_u, warp_n, angle_u, chmask_u);

    aug_kernel<<<GRID_PERSIST, 256>>>(
        (const float4*)x, (const float4*)noise, (float4*)out);
}

// round 12
// speedup vs baseline: 1.1408x; 1.1408x over previous
#include <cuda_runtime.h>
#include <math.h>

#define BB 512
#define TT 2048
#define CC 64

__device__ int   g_i0[TT];
__device__ float g_w0[TT];
__device__ float g_w1[TT];
__device__ float g_ca[BB];
__device__ float g_sa[BB];
__device__ float g_mask[CC];

// Slim one-block prep: 256 threads, all active, coalesced float4 loads of
// warp_noise, shfl-based scan.
__global__ void __launch_bounds__(256) prep_kernel(
    const float* __restrict__ scale_u,
    const float4* __restrict__ warp_noise4,   // TT/4 = 512 float4
    const float* __restrict__ angle_u,
    const float* __restrict__ chmask_u)
{
    __shared__ float cum[TT];
    __shared__ float wsum[8];
    const int tid  = threadIdx.x;         // 256 threads
    const int lane = tid & 31;
    const int wid  = tid >> 5;            // 8 warps
    const float k = 0.2f / (float)TT;     // TW_SIGMA / T

    // 8 contiguous elements per thread via two coalesced float4 loads
    const float4 a = __ldg(warp_noise4 + tid * 2);
    const float4 c = __ldg(warp_noise4 + tid * 2 + 1);
    float loc[8];
    loc[0] = a.x * k;
    loc[1] = loc[0] + a.y * k;
    loc[2] = loc[1] + a.z * k;
    loc[3] = loc[2] + a.w * k;
    loc[4] = loc[3] + c.x * k;
    loc[5] = loc[4] + c.y * k;
    loc[6] = loc[5] + c.z * k;
    loc[7] = loc[6] + c.w * k;

    const float myTotal = loc[7];
    float inc = myTotal;                  // warp-inclusive scan of chunk totals
    #pragma unroll
    for (int d = 1; d < 32; d <<= 1) {
        float o = __shfl_up_sync(0xffffffffu, inc, d);
        if (lane >= d) inc += o;
    }
    if (lane == 31) wsum[wid] = inc;
    __syncthreads();
    if (tid == 0) {
        float acc = 0.f;
        #pragma unroll
        for (int j = 0; j < 8; j++) { float v = wsum[j]; wsum[j] = acc; acc += v; }
    }
    __syncthreads();
    {
        const float excl = (inc - myTotal) + wsum[wid];
        #pragma unroll
        for (int i = 0; i < 8; i++) cum[tid * 8 + i] = excl + loc[i];
    }
    __syncthreads();

    const float c0    = cum[0];
    const float denom = (cum[TT - 1] - c0) + 1e-8f;
    const float scale = 0.9f + __ldg(scale_u) * 0.2f;

    #pragma unroll
    for (int i = 0; i < 8; i++) {
        int t = tid * 8 + i;
        float w  = (cum[t] - c0) / denom;
        float tw = (float)t / (float)(TT - 1) + 0.2f * w;
        tw = fminf(fmaxf(tw, 0.f), 1.f);
        float pos = tw * (float)(TT - 1);
        int i0 = (int)floorf(pos);
        i0 = min(max(i0, 0), TT - 2);
        float frac = pos - (float)i0;
        g_i0[t] = i0;
        g_w0[t] = scale * (1.f - frac);
        g_w1[t] = scale * frac;
    }

    #pragma unroll
    for (int i = 0; i < 2; i++) {         // 512 batches / 256 threads
        int b = tid + i * 256;
        float ang = __ldg(angle_u + b) * 6.283185307179586f - 3.141592653589793f;
        g_ca[b] = cosf(ang);
        g_sa[b] = sinf(ang);
    }
    if (tid < CC) g_mask[tid] = (__ldg(chmask_u + tid) > 0.1f) ? 1.f : 0.f;
}

// Main pass (converged R5 layout): 16 contiguous threads per 64-channel row,
// each thread two adjacent t-rows -> 8 front-batched coalesced LDG.128.
// Plain (default-policy) stores: let writes accumulate in L2 and drain in
// bursts instead of evict-first streaming.
__global__ void __launch_bounds__(256) aug_kernel(
    const float4* __restrict__ x,
    const float4* __restrict__ nz,
    float4* __restrict__ out)
{
    const int gid   = blockIdx.x * 256 + threadIdx.x;
    const int lane  = gid & 15;           // float4 index within row
    const int p     = gid >> 4;           // row-pair index
    const int row0  = p * 2;              // b*T + t0 (t0 even)
    const int t0    = row0 & (TT - 1);
    const int t1    = t0 + 1;
    const int b     = row0 >> 11;         // T = 2048 = 2^11

    const int   i0a = g_i0[t0];
    const int   i0b = g_i0[t1];
    const float w0a = g_w0[t0], w1a = g_w1[t0];
    const float w0b = g_w0[t1], w1b = g_w1[t1];

    const size_t bb    = (size_t)b * TT;
    const size_t baseA = (bb + (size_t)i0a) * 16 + (size_t)lane;
    const size_t baseB = (bb + (size_t)i0b) * 16 + (size_t)lane;

    // 8 independent coalesced 128-bit loads, front-batched for MLP
    const float4 xa0 = __ldg(x  + baseA);
    const float4 xa1 = __ldg(x  + baseA + 16);
    const float4 xb0 = __ldg(x  + baseB);
    const float4 xb1 = __ldg(x  + baseB + 16);
    const float4 na0 = __ldg(nz + baseA);
    const float4 na1 = __ldg(nz + baseA + 16);
    const float4 nb0 = __ldg(nz + baseB);
    const float4 nb1 = __ldg(nz + baseB + 16);

    const float J = 0.01f;
    float4 va, vb;
    va.x = w0a * fmaf(J, na0.x, xa0.x) + w1a * fmaf(J, na1.x, xa1.x);
    va.y = w0a * fmaf(J, na0.y, xa0.y) + w1a * fmaf(J, na1.y, xa1.y);
    va.z = w0a * fmaf(J, na0.z, xa0.z) + w1a * fmaf(J, na1.z, xa1.z);
    va.w = w0a * fmaf(J, na0.w, xa0.w) + w1a * fmaf(J, na1.w, xa1.w);
    vb.x = w0b * fmaf(J, nb0.x, xb0.x) + w1b * fmaf(J, nb1.x, xb1.x);
    vb.y = w0b * fmaf(J, nb0.y, xb0.y) + w1b * fmaf(J, nb1.y, xb1.y);
    vb.z = w0b * fmaf(J, nb0.z, xb0.z) + w1b * fmaf(J, nb1.z, xb1.z);
    vb.w = w0b * fmaf(J, nb0.w, xb0.w) + w1b * fmaf(J, nb1.w, xb1.w);

    if (lane == 0) {  // channels 0,1 rotation (both rows, same batch)
        const float ca = g_ca[b], sa = g_sa[b];
        float r0 = ca * va.x - sa * va.y;
        float r1 = sa * va.x + ca * va.y;
        va.x = r0; va.y = r1;
        r0 = ca * vb.x - sa * vb.y;
        r1 = sa * vb.x + ca * vb.y;
        vb.x = r0; vb.y = r1;
    }

    const float4 m = reinterpret_cast<const float4*>(g_mask)[lane];
    va.x *= m.x; va.y *= m.y; va.z *= m.z; va.w *= m.w;
    vb.x *= m.x; vb.y *= m.y; vb.z *= m.z; vb.w *= m.w;

    const size_t ob = (size_t)row0 * 16 + (size_t)lane;
    out[ob]      = va;
    out[ob + 16] = vb;
}

extern "C" void kernel_launch(void* const* d_in, const int* in_sizes, int n_in,
                              void* d_out, int out_size)
{
    const float* x        = (const float*)d_in[0];
    const float* noise    = (const float*)d_in[1];
    const float* scale_u  = (const float*)d_in[2];
    const float* warp_n   = (const float*)d_in[3];
    const float* angle_u  = (const float*)d_in[4];
    const float* chmask_u = (const float*)d_in[5];
    float* out = (float*)d_out;

    prep_kernel<<<1, 256>>>(scale_u, (const float4*)warp_n, angle_u, chmask_u);

    // B*T/2 row-pairs * 16 threads each, 256-thread blocks
    const int total_threads = BB * TT * 8;
    aug_kernel<<<total_threads / 256, 256>>>(
        (const float4*)x, (const float4*)noise, (float4*)out);
}